// round 6
// baseline (speedup 1.0000x reference)
#include <cuda_runtime.h>
#include <cuda_bf16.h>
#include <stdint.h>

#define NUM_NODES 10000
#define NUM_EDGES 640000
#define GNN_IN    128
#define HID       256

// Per-node tables: PAB[node][0:256]  = x[node]@W1[0:128] + b1  (b1 folded)
//                  PAB[node][256:512] = x[node]@W1[128:256]
__device__ __align__(16) __nv_bfloat16 g_pab[NUM_NODES * 512];

// ---------------------------------------------------------------------------
// Kernel 1: precompute GEMM  [10000 x 128] @ [128 x 512] -> bf16 tables
// ---------------------------------------------------------------------------
#define TM 64
#define TN 128
#define KC 16

__global__ __launch_bounds__(256) void precompute_kernel(
    const float* __restrict__ x, const float* __restrict__ w1,
    const float* __restrict__ b1)
{
    __shared__ float As[KC][TM + 1];
    __shared__ float Bs[KC][TN];

    const int m0  = blockIdx.y * TM;
    const int n0  = blockIdx.x * TN;
    const int tid = threadIdx.x;

    const int tm = tid & 15;
    const int tn = tid >> 4;

    const float* wptr = (n0 < 256) ? (w1 + n0) : (w1 + 128 * HID + (n0 - 256));

    const int a_kk = tid & 15;
    const int a_mm = tid >> 4;
    const int b_nn = (tid & 31) * 4;
    const int b_kk = tid >> 5;

    float acc[4][8];
#pragma unroll
    for (int r = 0; r < 4; r++)
#pragma unroll
        for (int c = 0; c < 8; c++) acc[r][c] = 0.f;

    for (int k0 = 0; k0 < GNN_IN; k0 += KC) {
#pragma unroll
        for (int i = 0; i < 4; i++) {
            int mm = a_mm + i * 16;
            int gm = m0 + mm;
            As[a_kk][mm] = (gm < NUM_NODES) ? x[gm * GNN_IN + k0 + a_kk] : 0.f;
        }
#pragma unroll
        for (int i = 0; i < 2; i++) {
            int kk = b_kk + i * 8;
            float4 v = *(const float4*)(wptr + (size_t)(k0 + kk) * HID + b_nn);
            *(float4*)&Bs[kk][b_nn] = v;
        }
        __syncthreads();

#pragma unroll
        for (int kk = 0; kk < KC; kk++) {
            float a[4], b[8];
#pragma unroll
            for (int r = 0; r < 4; r++) a[r] = As[kk][tm * 4 + r];
            *(float4*)&b[0] = *(const float4*)&Bs[kk][tn * 8];
            *(float4*)&b[4] = *(const float4*)&Bs[kk][tn * 8 + 4];
#pragma unroll
            for (int r = 0; r < 4; r++)
#pragma unroll
                for (int c = 0; c < 8; c++)
                    acc[r][c] = fmaf(a[r], b[c], acc[r][c]);
        }
        __syncthreads();
    }

    float badd[8];
#pragma unroll
    for (int c = 0; c < 8; c++)
        badd[c] = (n0 < 256) ? b1[n0 + tn * 8 + c] : 0.f;

#pragma unroll
    for (int r = 0; r < 4; r++) {
        int gm = m0 + tm * 4 + r;
        if (gm < NUM_NODES) {
            __nv_bfloat16* dst = g_pab + (size_t)gm * 512 + n0 + tn * 8;
#pragma unroll
            for (int c = 0; c < 8; c += 2) {
                __nv_bfloat162 p;
                p.x = __float2bfloat16_rn(acc[r][c]     + badd[c]);
                p.y = __float2bfloat16_rn(acc[r][c + 1] + badd[c + 1]);
                *(__nv_bfloat162*)(dst + c) = p;
            }
        }
    }
}

// ---------------------------------------------------------------------------
// Packed f32x2 helpers (Blackwell FFMA2 path) — exactly the R3 arithmetic
// ---------------------------------------------------------------------------
__device__ __forceinline__ unsigned long long pack_f32x2(float lo, float hi) {
    unsigned long long r;
    asm("mov.b64 %0, {%1, %2};" : "=l"(r) : "f"(lo), "f"(hi));
    return r;
}
__device__ __forceinline__ void unpack_f32x2(unsigned long long v, float& lo, float& hi) {
    asm("mov.b64 {%0, %1}, %2;" : "=f"(lo), "=f"(hi) : "l"(v));
}
__device__ __forceinline__ unsigned long long fma_f32x2(
    unsigned long long a, unsigned long long b, unsigned long long c) {
    unsigned long long r;
    asm("fma.rn.f32x2 %0, %1, %2, %3;" : "=l"(r) : "l"(a), "l"(b), "l"(c));
    return r;
}

__device__ __forceinline__ uint4 gatherA(int node, int j0) {
    return *(const uint4*)(g_pab + (size_t)node * 512 + j0);
}
__device__ __forceinline__ uint4 gatherB(int node, int j0) {
    return *(const uint4*)(g_pab + (size_t)node * 512 + 256 + j0);
}

__device__ __forceinline__ float edge_mlp(
    uint4 pa, uint4 pb, float4 d,
    const unsigned long long wcp[4][4], const float w2r[8])
{
    unsigned long long dd0 = pack_f32x2(d.x, d.x);
    unsigned long long dd1 = pack_f32x2(d.y, d.y);
    unsigned long long dd2 = pack_f32x2(d.z, d.z);
    unsigned long long dd3 = pack_f32x2(d.w, d.w);

    const unsigned* A = (const unsigned*)&pa;
    const unsigned* B = (const unsigned*)&pb;
    float acc = 0.f;
#pragma unroll
    for (int p = 0; p < 4; p++) {
        __nv_bfloat162 av = *(const __nv_bfloat162*)&A[p];
        __nv_bfloat162 bv = *(const __nv_bfloat162*)&B[p];
        __nv_bfloat162 sv = __hadd2(av, bv);
        unsigned w = *(const unsigned*)&sv;
        float lo = __uint_as_float(w << 16);
        float hi = __uint_as_float(w & 0xffff0000u);
        unsigned long long t2 = pack_f32x2(lo, hi);
        t2 = fma_f32x2(dd0, wcp[0][p], t2);
        t2 = fma_f32x2(dd1, wcp[1][p], t2);
        t2 = fma_f32x2(dd2, wcp[2][p], t2);
        t2 = fma_f32x2(dd3, wcp[3][p], t2);
        float t0, t1;
        unpack_f32x2(t2, t0, t1);
        t0 = fmaxf(t0, 0.f);
        t1 = fmaxf(t1, 0.f);
        acc = fmaf(t0, w2r[2 * p], acc);
        acc = fmaf(t1, w2r[2 * p + 1], acc);
    }
    return acc;
}

// ---------------------------------------------------------------------------
// Kernel 2: warp per edge, lane l owns hidden units [8l, 8l+8).
// 3-stage register pipeline: consume edge e while e+nw is resident and
// e+2nw is being issued -> gather latency (L2 ~260cyc) fully covered.
// ---------------------------------------------------------------------------
__global__ __launch_bounds__(128, 4) void edge_kernel(
    const int*   __restrict__ edge_index,
    const float* __restrict__ edge_dist,
    const float* __restrict__ w1,
    const float* __restrict__ w2,
    const float* __restrict__ b2,
    float* __restrict__ out)
{
    const int lane   = threadIdx.x & 31;
    const int warp   = blockIdx.x * (blockDim.x >> 5) + (threadIdx.x >> 5);
    const int nw     = gridDim.x * (blockDim.x >> 5);
    const int j0     = lane * 8;

    unsigned long long wcp[4][4];
    float w2r[8];
#pragma unroll
    for (int i = 0; i < 8; i++) w2r[i] = w2[j0 + i];
#pragma unroll
    for (int r = 0; r < 4; r++)
#pragma unroll
        for (int p = 0; p < 4; p++)
            wcp[r][p] = pack_f32x2(w1[(size_t)(256 + r) * HID + j0 + 2 * p],
                                   w1[(size_t)(256 + r) * HID + j0 + 2 * p + 1]);
    const float bias2 = b2[0];

    const int2*   idx2  = (const int2*)edge_index;
    const float4* dist4 = (const float4*)edge_dist;

    int e = warp;                      // edge consumed by the next copy
    if (e >= NUM_EDGES) return;

    // Prologue: fill slots 0 (edge e) and 1 (edge e+nw); pending idx for e+2nw.
    int e1c = min(e + nw, NUM_EDGES - 1);
    int e2c = min(e + 2 * nw, NUM_EDGES - 1);
    int2 ia = idx2[e];
    int2 ib = idx2[e1c];
    int2 iC = idx2[e2c];               // pending: idx of edge e+2nw

    uint4 A0 = gatherA(ia.x, j0), B0 = gatherB(ia.y, j0);
    uint4 A1 = gatherA(ib.x, j0), B1 = gatherB(ib.y, j0);
    float4 D0 = dist4[e];
    float4 D1 = dist4[e1c];
    uint4 A2, B2;
    float4 D2;

#define PIPE_BODY(Ac, Bc, Dc, Af, Bf, Df)                                     \
    {                                                                          \
        /* issue gathers for edge e+2nw into the fill slot */                  \
        int efc = min(e + 2 * nw, NUM_EDGES - 1);                              \
        Af = gatherA(iC.x, j0);                                                \
        Bf = gatherB(iC.y, j0);                                                \
        Df = dist4[efc];                                                       \
        int enc = min(e + 3 * nw, NUM_EDGES - 1);                              \
        iC = idx2[enc];                                                        \
        /* consume the oldest slot (edge e) */                                 \
        float acc = edge_mlp(Ac, Bc, Dc, wcp, w2r);                            \
        acc += __shfl_xor_sync(0xffffffffu, acc, 16);                          \
        acc += __shfl_xor_sync(0xffffffffu, acc, 8);                           \
        acc += __shfl_xor_sync(0xffffffffu, acc, 4);                           \
        acc += __shfl_xor_sync(0xffffffffu, acc, 2);                           \
        acc += __shfl_xor_sync(0xffffffffu, acc, 1);                           \
        if (lane == 0) {                                                       \
            float z = acc + bias2;                                             \
            out[e] = 1.f / (1.f + __expf(-z));                                 \
        }                                                                      \
        e += nw;                                                               \
        if (e >= NUM_EDGES) return;                                            \
    }

    for (;;) {
        PIPE_BODY(A0, B0, D0, A2, B2, D2)   // consume slot0, fill slot2
        PIPE_BODY(A1, B1, D1, A0, B0, D0)   // consume slot1, fill slot0
        PIPE_BODY(A2, B2, D2, A1, B1, D1)   // consume slot2, fill slot1
    }
#undef PIPE_BODY
}

// ---------------------------------------------------------------------------
extern "C" void kernel_launch(void* const* d_in, const int* in_sizes, int n_in,
                              void* d_out, int out_size) {
    const float* x          = (const float*)d_in[0];
    const int*   edge_index = (const int*)d_in[1];
    const float* edge_dist  = (const float*)d_in[2];
    const float* w1         = (const float*)d_in[3];
    const float* b1         = (const float*)d_in[4];
    const float* w2         = (const float*)d_in[5];
    const float* b2         = (const float*)d_in[6];
    float*       out        = (float*)d_out;

    dim3 g1(512 / TN, (NUM_NODES + TM - 1) / TM);
    precompute_kernel<<<g1, 256>>>(x, w1, b1);

    edge_kernel<<<2368, 128>>>(edge_index, edge_dist, w1, w2, b2, out);
}

// round 7
// speedup vs baseline: 1.2410x; 1.2410x over previous
#include <cuda_runtime.h>
#include <cuda_bf16.h>
#include <stdint.h>

#define NUM_NODES 10000
#define NUM_EDGES 640000
#define GNN_IN    128
#define HID       256

// Per-node tables: PAB[node][0:256]  = x[node]@W1[0:128] + b1  (b1 folded)
//                  PAB[node][256:512] = x[node]@W1[128:256]
__device__ __align__(16) __nv_bfloat16 g_pab[NUM_NODES * 512];

// ---------------------------------------------------------------------------
// Packed f32x2 helpers (Blackwell FFMA2 path)
// ---------------------------------------------------------------------------
__device__ __forceinline__ unsigned long long pack_f32x2(float lo, float hi) {
    unsigned long long r;
    asm("mov.b64 %0, {%1, %2};" : "=l"(r) : "f"(lo), "f"(hi));
    return r;
}
__device__ __forceinline__ void unpack_f32x2(unsigned long long v, float& lo, float& hi) {
    asm("mov.b64 {%0, %1}, %2;" : "=f"(lo), "=f"(hi) : "l"(v));
}
__device__ __forceinline__ unsigned long long fma_f32x2(
    unsigned long long a, unsigned long long b, unsigned long long c) {
    unsigned long long r;
    asm("fma.rn.f32x2 %0, %1, %2, %3;" : "=l"(r) : "l"(a), "l"(b), "l"(c));
    return r;
}

// ---------------------------------------------------------------------------
// Kernel 1: precompute GEMM  [10000 x 128] @ [128 x 512] -> bf16 tables
// FFMA2 inner loop: 16 fma.f32x2 per k-step (bit-identical to 32 FFMA).
// ---------------------------------------------------------------------------
#define TM 64
#define TN 128
#define KC 16

__global__ __launch_bounds__(256) void precompute_kernel(
    const float* __restrict__ x, const float* __restrict__ w1,
    const float* __restrict__ b1)
{
    __shared__ float As[KC][TM + 4];   // +4 pad keeps rows 16B-aligned
    __shared__ float Bs[KC][TN];

    const int m0  = blockIdx.y * TM;
    const int n0  = blockIdx.x * TN;
    const int tid = threadIdx.x;

    const int tm = tid & 15;
    const int tn = tid >> 4;

    const float* wptr = (n0 < 256) ? (w1 + n0) : (w1 + 128 * HID + (n0 - 256));

    const int a_kk = tid & 15;
    const int a_mm = tid >> 4;
    const int b_nn = (tid & 31) * 4;
    const int b_kk = tid >> 5;

    // acc2[r][c] covers output rows (tm*4+r), col pair (tn*8+2c, tn*8+2c+1)
    unsigned long long acc2[4][4];
#pragma unroll
    for (int r = 0; r < 4; r++)
#pragma unroll
        for (int c = 0; c < 4; c++) acc2[r][c] = 0ULL;

    for (int k0 = 0; k0 < GNN_IN; k0 += KC) {
#pragma unroll
        for (int i = 0; i < 4; i++) {
            int mm = a_mm + i * 16;
            int gm = m0 + mm;
            As[a_kk][mm] = (gm < NUM_NODES) ? x[gm * GNN_IN + k0 + a_kk] : 0.f;
        }
#pragma unroll
        for (int i = 0; i < 2; i++) {
            int kk = b_kk + i * 8;
            float4 v = *(const float4*)(wptr + (size_t)(k0 + kk) * HID + b_nn);
            *(float4*)&Bs[kk][b_nn] = v;
        }
        __syncthreads();

#pragma unroll
        for (int kk = 0; kk < KC; kk++) {
            float4 av = *(const float4*)&As[kk][tm * 4];       // rows, LDS.128
            float4 b0 = *(const float4*)&Bs[kk][tn * 8];       // cols 0..3
            float4 b1v = *(const float4*)&Bs[kk][tn * 8 + 4];  // cols 4..7

            unsigned long long bp[4];
            bp[0] = pack_f32x2(b0.x, b0.y);
            bp[1] = pack_f32x2(b0.z, b0.w);
            bp[2] = pack_f32x2(b1v.x, b1v.y);
            bp[3] = pack_f32x2(b1v.z, b1v.w);

            float ar[4] = {av.x, av.y, av.z, av.w};
#pragma unroll
            for (int r = 0; r < 4; r++) {
                unsigned long long a2 = pack_f32x2(ar[r], ar[r]);
#pragma unroll
                for (int c = 0; c < 4; c++)
                    acc2[r][c] = fma_f32x2(a2, bp[c], acc2[r][c]);
            }
        }
        __syncthreads();
    }

    float badd[8];
#pragma unroll
    for (int c = 0; c < 8; c++)
        badd[c] = (n0 < 256) ? b1[n0 + tn * 8 + c] : 0.f;

#pragma unroll
    for (int r = 0; r < 4; r++) {
        int gm = m0 + tm * 4 + r;
        if (gm < NUM_NODES) {
            __nv_bfloat16* dst = g_pab + (size_t)gm * 512 + n0 + tn * 8;
#pragma unroll
            for (int c = 0; c < 4; c++) {
                float lo, hi;
                unpack_f32x2(acc2[r][c], lo, hi);
                __nv_bfloat162 p;
                p.x = __float2bfloat16_rn(lo + badd[2 * c]);
                p.y = __float2bfloat16_rn(hi + badd[2 * c + 1]);
                *(__nv_bfloat162*)(dst + 2 * c) = p;
            }
        }
    }
}

// ---------------------------------------------------------------------------
// Kernel 2: warp per edge pair, lane l owns hidden units [8l, 8l+8).
// EXACT R3 structure (best measured: 107.6 us).
// ---------------------------------------------------------------------------
__device__ __forceinline__ uint4 gatherA(int node, int j0) {
    return *(const uint4*)(g_pab + (size_t)node * 512 + j0);
}
__device__ __forceinline__ uint4 gatherB(int node, int j0) {
    return *(const uint4*)(g_pab + (size_t)node * 512 + 256 + j0);
}

__device__ __forceinline__ float edge_mlp(
    uint4 pa, uint4 pb, float4 d,
    const unsigned long long wcp[4][4], const float w2r[8])
{
    unsigned long long dd0 = pack_f32x2(d.x, d.x);
    unsigned long long dd1 = pack_f32x2(d.y, d.y);
    unsigned long long dd2 = pack_f32x2(d.z, d.z);
    unsigned long long dd3 = pack_f32x2(d.w, d.w);

    const unsigned* A = (const unsigned*)&pa;
    const unsigned* B = (const unsigned*)&pb;
    float acc = 0.f;
#pragma unroll
    for (int p = 0; p < 4; p++) {
        __nv_bfloat162 av = *(const __nv_bfloat162*)&A[p];
        __nv_bfloat162 bv = *(const __nv_bfloat162*)&B[p];
        __nv_bfloat162 sv = __hadd2(av, bv);
        unsigned w = *(const unsigned*)&sv;
        float lo = __uint_as_float(w << 16);
        float hi = __uint_as_float(w & 0xffff0000u);
        unsigned long long t2 = pack_f32x2(lo, hi);
        t2 = fma_f32x2(dd0, wcp[0][p], t2);
        t2 = fma_f32x2(dd1, wcp[1][p], t2);
        t2 = fma_f32x2(dd2, wcp[2][p], t2);
        t2 = fma_f32x2(dd3, wcp[3][p], t2);
        float t0, t1;
        unpack_f32x2(t2, t0, t1);
        t0 = fmaxf(t0, 0.f);
        t1 = fmaxf(t1, 0.f);
        acc = fmaf(t0, w2r[2 * p], acc);
        acc = fmaf(t1, w2r[2 * p + 1], acc);
    }
    return acc;
}

__global__ __launch_bounds__(128, 4) void edge_kernel(
    const int*   __restrict__ edge_index,
    const float* __restrict__ edge_dist,
    const float* __restrict__ w1,
    const float* __restrict__ w2,
    const float* __restrict__ b2,
    float* __restrict__ out)
{
    const int lane   = threadIdx.x & 31;
    const int warp   = blockIdx.x * (blockDim.x >> 5) + (threadIdx.x >> 5);
    const int nwarps = gridDim.x * (blockDim.x >> 5);
    const int j0     = lane * 8;

    unsigned long long wcp[4][4];
    float w2r[8];
#pragma unroll
    for (int i = 0; i < 8; i++) w2r[i] = w2[j0 + i];
#pragma unroll
    for (int r = 0; r < 4; r++)
#pragma unroll
        for (int p = 0; p < 4; p++)
            wcp[r][p] = pack_f32x2(w1[(size_t)(256 + r) * HID + j0 + 2 * p],
                                   w1[(size_t)(256 + r) * HID + j0 + 2 * p + 1]);
    const float bias2 = b2[0];

    const int stride = nwarps * 2;
    int ec = warp * 2;
    if (ec >= NUM_EDGES) return;
    int en  = ec + stride;
    int enc = (en < NUM_EDGES - 2) ? en : (NUM_EDGES - 2);

    const int2*   idx2  = (const int2*)edge_index;
    const float4* dist4 = (const float4*)edge_dist;

    int2 ia0 = idx2[ec], ib0 = idx2[ec + 1];
    uint4 pa0 = gatherA(ia0.x, j0), pb0 = gatherB(ia0.y, j0);
    uint4 pa1 = gatherA(ib0.x, j0), pb1 = gatherB(ib0.y, j0);
    float4 da0 = dist4[ec], db0 = dist4[ec + 1];
    int2 ja = idx2[enc], jb = idx2[enc + 1];

    for (;;) {
        // ---- half A: consume set0 (edges ec,ec+1); prefetch set1 ----
        uint4 qa0 = gatherA(ja.x, j0), qb0 = gatherB(ja.y, j0);
        uint4 qa1 = gatherA(jb.x, j0), qb1 = gatherB(jb.y, j0);
        float4 ea0 = dist4[enc], eb0 = dist4[enc + 1];
        int e2  = en + stride;
        int e2c = (e2 < NUM_EDGES - 2) ? e2 : (NUM_EDGES - 2);
        ja = idx2[e2c];  jb = idx2[e2c + 1];

        {
            float a0 = edge_mlp(pa0, pb0, da0, wcp, w2r);
            float a1 = edge_mlp(pa1, pb1, db0, wcp, w2r);
            float s0 = a0 + __shfl_xor_sync(0xffffffffu, a0, 16);
            float s1 = a1 + __shfl_xor_sync(0xffffffffu, a1, 16);
            float c  = (lane < 16) ? s0 : s1;
            c += __shfl_xor_sync(0xffffffffu, c, 8);
            c += __shfl_xor_sync(0xffffffffu, c, 4);
            c += __shfl_xor_sync(0xffffffffu, c, 2);
            c += __shfl_xor_sync(0xffffffffu, c, 1);
            if ((lane & 15) == 0) {
                float z = c + bias2;
                out[ec + (lane >> 4)] = 1.f / (1.f + __expf(-z));
            }
        }

        ec = en;
        if (ec >= NUM_EDGES) break;
        en = e2;  enc = e2c;

        // ---- half B: consume set1; prefetch set0 ----
        pa0 = gatherA(ja.x, j0);  pb0 = gatherB(ja.y, j0);
        pa1 = gatherA(jb.x, j0);  pb1 = gatherB(jb.y, j0);
        da0 = dist4[enc];  db0 = dist4[enc + 1];
        int e3  = en + stride;
        int e3c = (e3 < NUM_EDGES - 2) ? e3 : (NUM_EDGES - 2);
        ja = idx2[e3c];  jb = idx2[e3c + 1];

        {
            float a0 = edge_mlp(qa0, qb0, ea0, wcp, w2r);
            float a1 = edge_mlp(qa1, qb1, eb0, wcp, w2r);
            float s0 = a0 + __shfl_xor_sync(0xffffffffu, a0, 16);
            float s1 = a1 + __shfl_xor_sync(0xffffffffu, a1, 16);
            float c  = (lane < 16) ? s0 : s1;
            c += __shfl_xor_sync(0xffffffffu, c, 8);
            c += __shfl_xor_sync(0xffffffffu, c, 4);
            c += __shfl_xor_sync(0xffffffffu, c, 2);
            c += __shfl_xor_sync(0xffffffffu, c, 1);
            if ((lane & 15) == 0) {
                float z = c + bias2;
                out[ec + (lane >> 4)] = 1.f / (1.f + __expf(-z));
            }
        }

        ec = en;
        if (ec >= NUM_EDGES) break;
        en = e3;  enc = e3c;
    }
}

// ---------------------------------------------------------------------------
extern "C" void kernel_launch(void* const* d_in, const int* in_sizes, int n_in,
                              void* d_out, int out_size) {
    const float* x          = (const float*)d_in[0];
    const int*   edge_index = (const int*)d_in[1];
    const float* edge_dist  = (const float*)d_in[2];
    const float* w1         = (const float*)d_in[3];
    const float* b1         = (const float*)d_in[4];
    const float* w2         = (const float*)d_in[5];
    const float* b2         = (const float*)d_in[6];
    float*       out        = (float*)d_out;

    dim3 g1(512 / TN, (NUM_NODES + TM - 1) / TM);
    precompute_kernel<<<g1, 256>>>(x, w1, b1);

    edge_kernel<<<2368, 128>>>(edge_index, edge_dist, w1, w2, b2, out);
}